// round 8
// baseline (speedup 1.0000x reference)
#include <cuda_runtime.h>
#include <cuda_fp16.h>

#define N_NODES 65536
#define N_EDGES 1048576
#define HID 80
#define NPB 16   // nodes per k_trans block

// ---------------- static scratch (no allocations allowed) ----------------
__device__ __half2 g_hh[N_NODES * 40];       // h fp16: 40 half2/node (10.5 MB)
__device__ uint2   g_A[N_NODES * 80];        // aggregate fp16: 4 sections x 80 vals (42 MB)
__device__ int     g_deg[N_NODES];
__device__ int     g_rowptr[N_NODES + 1];
__device__ int     g_cursor[N_NODES];
__device__ int     g_csrc[N_EDGES];
__device__ uint2   g_coefh[N_EDGES];         // 4 x fp16 coef (8 MB)

// e3nn fan-in norms * 1/sqrt(2) * 1/sqrt(DEG=16)
#define K1C (0.03125f)
#define K2C (0.025515518f)
#define K3C (0.03125f)
#define K4C (0.044194174f)

__device__ __forceinline__ unsigned int h2u(float a, float b) {
    __half2 h = __floats2half2_rn(a, b);
    return *(const unsigned int*)&h;
}
__device__ __forceinline__ uint2 pack4h(float a, float b, float c, float d) {
    uint2 r; r.x = h2u(a, b); r.y = h2u(c, d); return r;
}
__device__ __forceinline__ float4 unpack4h(uint2 p) {
    float2 lo = __half22float2(*(const __half2*)&p.x);
    float2 hi = __half22float2(*(const __half2*)&p.y);
    return make_float4(lo.x, lo.y, hi.x, hi.y);
}

// ---------------- preprocessing ----------------
__global__ void k_zero(int* __restrict__ deg) {
    int i = blockIdx.x * blockDim.x + threadIdx.x;
    if (i < N_NODES) deg[i] = 0;
}

__global__ void k_hist(const int* __restrict__ dst, int* __restrict__ deg) {
    int e = blockIdx.x * blockDim.x + threadIdx.x;
    if (e < N_EDGES) atomicAdd(&deg[dst[e]], 1);
}

// single-block (1024 threads) exclusive scan over 65536 ints; each thread owns 64
__global__ __launch_bounds__(1024) void k_scan(
    const int* __restrict__ deg, int* __restrict__ rowptr, int* __restrict__ cursor)
{
    __shared__ int wsum[32];
    int tid = threadIdx.x;
    int lane = tid & 31, wid = tid >> 5;
    int base = tid * 64;
    const int4* d4 = (const int4*)(deg + base);
    int s = 0;
#pragma unroll
    for (int i = 0; i < 16; i++) {
        int4 v = d4[i];
        s += v.x + v.y + v.z + v.w;
    }
    int v = s;
#pragma unroll
    for (int d = 1; d < 32; d <<= 1) {
        int t = __shfl_up_sync(0xffffffffu, v, d);
        if (lane >= d) v += t;
    }
    if (lane == 31) wsum[wid] = v;
    __syncthreads();
    if (wid == 0) {
        int w = wsum[lane];
        int wv = w;
#pragma unroll
        for (int d = 1; d < 32; d <<= 1) {
            int t = __shfl_up_sync(0xffffffffu, wv, d);
            if (lane >= d) wv += t;
        }
        wsum[lane] = wv - w;
    }
    __syncthreads();
    int off = wsum[wid] + (v - s);
#pragma unroll
    for (int i = 0; i < 16; i++) {
        int4 dv = d4[i];
        int b = base + i * 4;
        rowptr[b + 0] = off; cursor[b + 0] = off; off += dv.x;
        rowptr[b + 1] = off; cursor[b + 1] = off; off += dv.y;
        rowptr[b + 2] = off; cursor[b + 2] = off; off += dv.z;
        rowptr[b + 3] = off; cursor[b + 3] = off; off += dv.w;
    }
    if (tid == 1023) rowptr[N_NODES] = off;
}

__global__ void k_csr(const int* __restrict__ src, const int* __restrict__ dst,
                      const float4* __restrict__ eattr,
                      int* __restrict__ cursor, int* __restrict__ csrc,
                      uint2* __restrict__ coefh) {
    int e = blockIdx.x * blockDim.x + threadIdx.x;
    if (e >= N_EDGES) return;
    int d = dst[e];
    int pos = atomicAdd(&cursor[d], 1);
    csrc[pos] = src[e];
    float4 cf = eattr[e];
    coefh[pos] = pack4h(cf.x, cf.y, cf.z, cf.w);   // (s2, v2x, v2y, v2z)
}

// ---------------- input embed: h = x @ W_in + b_in (fp16 out) ----------------
__global__ void k_input(const float* __restrict__ x, const float* __restrict__ W_in,
                        const float* __restrict__ b_in, __half2* __restrict__ hh) {
    int id = blockIdx.x * blockDim.x + threadIdx.x;   // N*40
    if (id >= N_NODES * 40) return;
    int n = id / 40, p = id % 40;
    int c0 = 2 * p, c1 = c0 + 1;
    const float* xr = x + n * 16;
    float a0 = b_in[c0], a1 = b_in[c1];
#pragma unroll
    for (int i = 0; i < 16; i++) {
        float xi = xr[i];
        a0 = fmaf(xi, W_in[i * HID + c0], a0);
        a1 = fmaf(xi, W_in[i * HID + c1], a1);
    }
    hh[id] = __floats2half2_rn(a0, a1);
}

// ---------------- aggregation: A[n] = sum_e coef_e (x) h[src_e]  ----------------
// one warp per node, 8 nodes per 256-thread block. Lane L<20 owns h elems 4L..4L+3.
// A layout per node: 4 sections (s,x,y,z) x 20 uint2 (fp16), i.e. A[n*80 + sec*20 + L]
__global__ __launch_bounds__(256) void k_agg(
    const uint2* __restrict__ hhu, const int* __restrict__ rowptr,
    const int* __restrict__ csrc, const uint2* __restrict__ coefh,
    uint2* __restrict__ A)
{
    __shared__ int    s_src[8][32];
    __shared__ float4 s_cf[8][32];
    int wid = threadIdx.x >> 5, lane = threadIdx.x & 31;
    int n = blockIdx.x * 8 + wid;
    int beg = rowptr[n], end = rowptr[n + 1];
    float4 r0 = {0,0,0,0}, r1 = {0,0,0,0}, r2 = {0,0,0,0}, r3 = {0,0,0,0};
    for (int base = beg; base < end; base += 32) {
        int cnt = min(32, end - base);
        __syncwarp();
        if (lane < cnt) {
            s_src[wid][lane] = csrc[base + lane];
            s_cf[wid][lane]  = unpack4h(coefh[base + lane]);
        }
        __syncwarp();
        if (lane < 20) {
#pragma unroll 4
            for (int i = 0; i < cnt; i++) {
                int s = s_src[wid][i];
                float4 cf = s_cf[wid][i];
                float4 f = unpack4h(hhu[s * 20 + lane]);
                r0.x = fmaf(cf.x, f.x, r0.x); r0.y = fmaf(cf.x, f.y, r0.y);
                r0.z = fmaf(cf.x, f.z, r0.z); r0.w = fmaf(cf.x, f.w, r0.w);
                r1.x = fmaf(cf.y, f.x, r1.x); r1.y = fmaf(cf.y, f.y, r1.y);
                r1.z = fmaf(cf.y, f.z, r1.z); r1.w = fmaf(cf.y, f.w, r1.w);
                r2.x = fmaf(cf.z, f.x, r2.x); r2.y = fmaf(cf.z, f.y, r2.y);
                r2.z = fmaf(cf.z, f.z, r2.z); r2.w = fmaf(cf.z, f.w, r2.w);
                r3.x = fmaf(cf.w, f.x, r3.x); r3.y = fmaf(cf.w, f.y, r3.y);
                r3.z = fmaf(cf.w, f.z, r3.z); r3.w = fmaf(cf.w, f.w, r3.w);
            }
        }
    }
    if (lane < 20) {
        uint2* An = A + n * 80;
        An[0 * 20 + lane] = pack4h(r0.x, r0.y, r0.z, r0.w);
        An[1 * 20 + lane] = pack4h(r1.x, r1.y, r1.z, r1.w);
        An[2 * 20 + lane] = pack4h(r2.x, r2.y, r2.z, r2.w);
        An[3 * 20 + lane] = pack4h(r3.x, r3.y, r3.z, r3.w);
    }
}

// ---------------- shared helpers for the A -> h transform ----------------
__device__ __forceinline__ void stage_trans(
    int tid, const uint2* __restrict__ A, int nb,
    const float* __restrict__ w1, const float* __restrict__ w2,
    const float* __restrict__ w3, const float* __restrict__ w4,
    float* s_w1, float* s_w2, float* s_w3, float* s_w4, float* s_A)
{
    for (int i = tid; i < 1024; i += 192) s_w1[i] = K1C * w1[i];
    for (int i = tid; i < 512;  i += 192) s_w2[i] = K2C * w2[i];
    for (int i = tid; i < 512;  i += 192) s_w3[i] = K3C * w3[i];
    for (int i = tid; i < 256;  i += 192) s_w4[i] = K4C * w4[i];
    const uint2* Ab = A + nb * 80;
    for (int i = tid; i < NPB * 80; i += 192) {
        int n = i / 80, r = i % 80, sec = r / 20, L = r % 20;
        float4 v = unpack4h(Ab[i]);
        *(float4*)&s_A[n * 320 + sec * 80 + 4 * L] = v;
    }
}

// core: thread (g, cp) computes 2 nodes x 2 channels from smem A
// s_A per node: [A_s(80) | A_x(80) | A_y(80) | A_z(80)]
__device__ __forceinline__ void trans_core(
    const float* s_A, const float* s_w1, const float* s_w2,
    const float* s_w3, const float* s_w4,
    int g, int cp, float* oA, float* oB)
{
    const float* AA = s_A + (2 * g) * 320;
    const float* AB = AA + 320;
    if (cp < 16) {
        int c0 = 2 * cp, c1 = c0 + 1;
        float pA0 = 0.f, pA1 = 0.f, pB0 = 0.f, pB1 = 0.f;
#pragma unroll
        for (int a = 0; a < 32; a++) {
            float u = s_w1[a * 32 + c0], v = s_w1[a * 32 + c1];
            float xA = AA[a], xB = AB[a];
            pA0 = fmaf(xA, u, pA0); pA1 = fmaf(xA, v, pA1);
            pB0 = fmaf(xB, u, pB0); pB1 = fmaf(xB, v, pB1);
        }
#pragma unroll
        for (int a = 0; a < 16; a++) {
            float u = s_w2[a * 32 + c0], v = s_w2[a * 32 + c1];
#pragma unroll
            for (int k = 0; k < 3; k++) {
                float tA = AA[80 + 80 * k + 32 + 3 * a + k];
                float tB = AB[80 + 80 * k + 32 + 3 * a + k];
                pA0 = fmaf(tA, u, pA0); pA1 = fmaf(tA, v, pA1);
                pB0 = fmaf(tB, u, pB0); pB1 = fmaf(tB, v, pB1);
            }
        }
        oA[0] = pA0; oA[1] = pA1; oB[0] = pB0; oB[1] = pB1;
    } else {
        int c0 = 2 * (cp - 16), c1 = c0 + 1;
        float rA[6] = {0,0,0,0,0,0}, rB[6] = {0,0,0,0,0,0};  // [c 0/1][k]
#pragma unroll
        for (int a = 0; a < 32; a++) {
            float u = s_w3[a * 16 + c0], v = s_w3[a * 16 + c1];
#pragma unroll
            for (int k = 0; k < 3; k++) {
                float tA = AA[80 + 80 * k + a];
                float tB = AB[80 + 80 * k + a];
                rA[k]     = fmaf(tA, u, rA[k]);     rA[3 + k] = fmaf(tA, v, rA[3 + k]);
                rB[k]     = fmaf(tB, u, rB[k]);     rB[3 + k] = fmaf(tB, v, rB[3 + k]);
            }
        }
#pragma unroll
        for (int a = 0; a < 16; a++) {
            float u = s_w4[a * 16 + c0], v = s_w4[a * 16 + c1];
#pragma unroll
            for (int k = 0; k < 3; k++) {
                float tA = AA[32 + 3 * a + k];
                float tB = AB[32 + 3 * a + k];
                rA[k]     = fmaf(tA, u, rA[k]);     rA[3 + k] = fmaf(tA, v, rA[3 + k]);
                rB[k]     = fmaf(tB, u, rB[k]);     rB[3 + k] = fmaf(tB, v, rB[3 + k]);
            }
        }
#pragma unroll
        for (int i = 0; i < 6; i++) { oA[i] = rA[i]; oB[i] = rB[i]; }
    }
}

__global__ __launch_bounds__(192) void k_trans(
    const uint2* __restrict__ A,
    const float* __restrict__ w1, const float* __restrict__ w2,
    const float* __restrict__ w3, const float* __restrict__ w4,
    __half2* __restrict__ hh)
{
    __shared__ float s_w1[1024], s_w2[512], s_w3[512], s_w4[256];
    __shared__ float s_A[NPB * 320];
    int tid = threadIdx.x;
    int nb = blockIdx.x * NPB;
    stage_trans(tid, A, nb, w1, w2, w3, w4, s_w1, s_w2, s_w3, s_w4, s_A);
    __syncthreads();
    int g = tid / 24, cp = tid % 24;
    float oA[6], oB[6];
    trans_core(s_A, s_w1, s_w2, s_w3, s_w4, g, cp, oA, oB);
    __half2* hA = hh + (nb + 2 * g) * 40;
    __half2* hB = hA + 40;
    if (cp < 16) {
        hA[cp] = __floats2half2_rn(oA[0], oA[1]);
        hB[cp] = __floats2half2_rn(oB[0], oB[1]);
    } else {
        int m = cp - 16;   // channels 2m,2m+1 -> half positions 32+6m..37+6m
        hA[16 + 3 * m + 0] = __floats2half2_rn(oA[0], oA[1]);
        hA[16 + 3 * m + 1] = __floats2half2_rn(oA[2], oA[3]);
        hA[16 + 3 * m + 2] = __floats2half2_rn(oA[4], oA[5]);
        hB[16 + 3 * m + 0] = __floats2half2_rn(oB[0], oB[1]);
        hB[16 + 3 * m + 1] = __floats2half2_rn(oB[2], oB[3]);
        hB[16 + 3 * m + 2] = __floats2half2_rn(oB[4], oB[5]);
    }
}

// wait: vector channel c components live at h[32+3c+k]; channels c0=2m, c1=2m+1 span
// h[32+6m .. 32+6m+5] = (t0x,t0y,t0z,t1x,t1y,t1z) — matches the writes above where
// oA = (t0x,t0y,t0z,t1x,t1y,t1z).

__global__ __launch_bounds__(192) void k_trans_final(
    const uint2* __restrict__ A,
    const float* __restrict__ w1, const float* __restrict__ w2,
    const float* __restrict__ w3, const float* __restrict__ w4,
    const float* __restrict__ W_out, const float* __restrict__ b_out,
    float* __restrict__ out)
{
    __shared__ float s_w1[1024], s_w2[512], s_w3[512], s_w4[256];
    __shared__ float s_A[NPB * 320];
    __shared__ float s_o[NPB][HID];
    __shared__ float s_Wo[HID * 8];
    int tid = threadIdx.x;
    int nb = blockIdx.x * NPB;
    stage_trans(tid, A, nb, w1, w2, w3, w4, s_w1, s_w2, s_w3, s_w4, s_A);
    for (int i = tid; i < HID * 8; i += 192) s_Wo[i] = W_out[i];
    __syncthreads();
    int g = tid / 24, cp = tid % 24;
    float oA[6], oB[6];
    trans_core(s_A, s_w1, s_w2, s_w3, s_w4, g, cp, oA, oB);
    int nA = 2 * g, nB = nA + 1;
    if (cp < 16) {
        int c0 = 2 * cp;
        s_o[nA][c0]     = fmaxf(oA[0], 0.f);
        s_o[nA][c0 + 1] = fmaxf(oA[1], 0.f);
        s_o[nB][c0]     = fmaxf(oB[0], 0.f);
        s_o[nB][c0 + 1] = fmaxf(oB[1], 0.f);
    } else {
        int m = cp - 16;
#pragma unroll
        for (int i = 0; i < 6; i++) {
            s_o[nA][32 + 6 * m + i] = fmaxf(oA[i], 0.f);
            s_o[nB][32 + 6 * m + i] = fmaxf(oB[i], 0.f);
        }
    }
    __syncthreads();
    if (tid < NPB * 8) {
        int node = tid / 8, o = tid % 8;
        float acc = b_out[o];
        const float* so = s_o[node];
#pragma unroll
        for (int c = 0; c < HID; c++)
            acc = fmaf(so[c], s_Wo[c * 8 + o], acc);
        out[(nb + node) * 8 + o] = acc;
    }
}

// ---------------- launch ----------------
extern "C" void kernel_launch(void* const* d_in, const int* in_sizes, int n_in,
                              void* d_out, int out_size) {
    const float* x     = (const float*)d_in[0];
    const int*   eidx  = (const int*)d_in[1];     // (2, E) int32: row0=src, row1=dst
    const float* eattr = (const float*)d_in[2];   // (E, 4)
    const float* W_in  = (const float*)d_in[3];
    const float* b_in  = (const float*)d_in[4];
    const float* tpw1  = (const float*)d_in[5];   // (3,32,32)
    const float* tpw2  = (const float*)d_in[6];   // (3,16,32)
    const float* tpw3  = (const float*)d_in[7];   // (3,32,16)
    const float* tpw4  = (const float*)d_in[8];   // (3,16,16)
    const float* W_out = (const float*)d_in[9];
    const float* b_out = (const float*)d_in[10];
    float* out = (float*)d_out;

    __half2 *hh; uint2 *A, *coefh; int *deg, *rowptr, *cursor, *csrc;
    cudaGetSymbolAddress((void**)&hh,     g_hh);
    cudaGetSymbolAddress((void**)&A,      g_A);
    cudaGetSymbolAddress((void**)&deg,    g_deg);
    cudaGetSymbolAddress((void**)&rowptr, g_rowptr);
    cudaGetSymbolAddress((void**)&cursor, g_cursor);
    cudaGetSymbolAddress((void**)&csrc,   g_csrc);
    cudaGetSymbolAddress((void**)&coefh,  g_coefh);

    const int* src = eidx;
    const int* dst = eidx + N_EDGES;

    // CSR build
    k_zero<<<N_NODES / 256, 256>>>(deg);
    k_hist<<<N_EDGES / 256, 256>>>(dst, deg);
    k_scan<<<1, 1024>>>(deg, rowptr, cursor);
    k_csr<<<N_EDGES / 256, 256>>>(src, dst, (const float4*)eattr, cursor, csrc, coefh);

    // input embed (fp16 h)
    k_input<<<(N_NODES * 40) / 256, 256>>>(x, W_in, b_in, hh);

    // layers 0,1: aggregate (reads hh, writes A) then transform (reads A, writes hh)
    for (int l = 0; l < 2; l++) {
        k_agg<<<N_NODES / 8, 256>>>((const uint2*)hh, rowptr, csrc, coefh, A);
        k_trans<<<N_NODES / NPB, 192>>>(A,
            tpw1 + l * 32 * 32, tpw2 + l * 16 * 32,
            tpw3 + l * 32 * 16, tpw4 + l * 16 * 16, hh);
    }

    // layer 2: aggregate then fused transform + readout
    k_agg<<<N_NODES / 8, 256>>>((const uint2*)hh, rowptr, csrc, coefh, A);
    k_trans_final<<<N_NODES / NPB, 192>>>(A,
        tpw1 + 2 * 32 * 32, tpw2 + 2 * 16 * 32,
        tpw3 + 2 * 32 * 16, tpw4 + 2 * 16 * 16, W_out, b_out, out);
}